// round 1
// baseline (speedup 1.0000x reference)
#include <cuda_runtime.h>
#include <stdint.h>
#include <math.h>

#define BATCH 32
#define CHAN  256
#define HH    56
#define WW    56
#define S     (HH*WW)      // 3136
#define S4    (S/4)        // 784
#define QSPLIT 4
#define CQ    (CHAN/QSPLIT) // 64
#define RNUM  1568          // removed_num = round(3136*0.5)

// scratch (no cudaMalloc allowed)
__device__ __align__(16) float g_part_max[QSPLIT*BATCH*S];
__device__ __align__(16) float g_part_sum[QSPLIT*BATCH*S];
__device__ __align__(16) float g_pool_max[BATCH*S];
__device__ __align__(16) float g_pool_avg[BATCH*S];
__device__ __align__(16) float g_y[BATCH*S];

// ---------------------------------------------------------------------------
// Kernel 1: partial channel max/sum. Each thread owns 4 consecutive spatial
// positions (float4) and 64 of the 256 channels. 392 blocks x 256 threads.
// ---------------------------------------------------------------------------
__global__ void pool_partial(const float* __restrict__ x) {
    int gid = blockIdx.x * blockDim.x + threadIdx.x;   // 0 .. 100351
    int q   = gid / (BATCH * S4);
    int rem = gid % (BATCH * S4);
    int b   = rem / S4;
    int s4  = rem % S4;

    const float4* p = reinterpret_cast<const float4*>(x)
                    + (size_t)(b * CHAN + q * CQ) * S4 + s4;

    float4 mx = make_float4(-INFINITY, -INFINITY, -INFINITY, -INFINITY);
    float4 sm = make_float4(0.f, 0.f, 0.f, 0.f);

    #pragma unroll 8
    for (int c = 0; c < CQ; ++c) {
        float4 v = __ldg(p + (size_t)c * S4);
        mx.x = fmaxf(mx.x, v.x); mx.y = fmaxf(mx.y, v.y);
        mx.z = fmaxf(mx.z, v.z); mx.w = fmaxf(mx.w, v.w);
        sm.x += v.x; sm.y += v.y; sm.z += v.z; sm.w += v.w;
    }

    int o = (q * BATCH + b) * S4 + s4;
    reinterpret_cast<float4*>(g_part_max)[o] = mx;
    reinterpret_cast<float4*>(g_part_sum)[o] = sm;
}

// ---------------------------------------------------------------------------
// Kernel 2: fold the 4 partials -> pooled max / avg
// ---------------------------------------------------------------------------
__global__ void pool_combine() {
    int gid = blockIdx.x * blockDim.x + threadIdx.x;
    if (gid >= BATCH * S4) return;

    float4 mx = make_float4(-INFINITY, -INFINITY, -INFINITY, -INFINITY);
    float4 sm = make_float4(0.f, 0.f, 0.f, 0.f);
    int b  = gid / S4;
    int s4 = gid % S4;
    #pragma unroll
    for (int q = 0; q < QSPLIT; ++q) {
        int o = (q * BATCH + b) * S4 + s4;
        float4 m = reinterpret_cast<const float4*>(g_part_max)[o];
        float4 s = reinterpret_cast<const float4*>(g_part_sum)[o];
        mx.x = fmaxf(mx.x, m.x); mx.y = fmaxf(mx.y, m.y);
        mx.z = fmaxf(mx.z, m.z); mx.w = fmaxf(mx.w, m.w);
        sm.x += s.x; sm.y += s.y; sm.z += s.z; sm.w += s.w;
    }
    const float inv = 1.0f / (float)CHAN;
    sm.x *= inv; sm.y *= inv; sm.z *= inv; sm.w *= inv;
    reinterpret_cast<float4*>(g_pool_max)[gid] = mx;
    reinterpret_cast<float4*>(g_pool_avg)[gid] = sm;
}

// ---------------------------------------------------------------------------
// Kernel 3: 3x3 conv (2ch -> 1ch, pad 1) + sigmoid. Cross-correlation, OIHW.
// ---------------------------------------------------------------------------
__global__ void conv_sig(const float* __restrict__ w) {
    __shared__ float ws[18];
    if (threadIdx.x < 18) ws[threadIdx.x] = w[threadIdx.x];
    __syncthreads();

    int gid = blockIdx.x * blockDim.x + threadIdx.x;
    if (gid >= BATCH * S) return;
    int b  = gid / S;
    int s  = gid % S;
    int oh = s / WW;
    int ow = s % WW;

    const float* pm = g_pool_max + b * S;
    const float* pa = g_pool_avg + b * S;

    float acc = 0.f;
    #pragma unroll
    for (int ky = 0; ky < 3; ++ky) {
        int ih = oh + ky - 1;
        if (ih < 0 || ih >= HH) continue;
        #pragma unroll
        for (int kx = 0; kx < 3; ++kx) {
            int iw = ow + kx - 1;
            if (iw < 0 || iw >= WW) continue;
            int ii = ih * WW + iw;
            acc = fmaf(pm[ii], ws[ky * 3 + kx], acc);      // ci=0: max channel
            acc = fmaf(pa[ii], ws[9 + ky * 3 + kx], acc);  // ci=1: avg channel
        }
    }
    g_y[gid] = 1.0f / (1.0f + expf(-acc));
}

// ---------------------------------------------------------------------------
// Kernel 4: per-batch exact select of the RNUM smallest values and zero them.
// Sigmoid output > 0, so IEEE fp32 bits order == float order. 4-pass radix
// select (8 bits/pass) finds T = value at rank RNUM-1 plus count(< T); ties
// at T are zeroed in ascending index order (stable-argsort semantics).
// One block per batch, 256 threads.
// ---------------------------------------------------------------------------
__global__ void topk_mask() {
    __shared__ unsigned int uvals[S];
    __shared__ int hist[256];
    __shared__ unsigned int s_prefix;
    __shared__ int s_r, s_less;
    __shared__ int tieIdx[64];
    __shared__ int tieCount;

    int b = blockIdx.x;
    int t = threadIdx.x;
    float* yb = g_y + b * S;

    for (int i = t; i < S; i += 256) uvals[i] = __float_as_uint(yb[i]);
    if (t == 0) { s_r = RNUM - 1; s_less = 0; s_prefix = 0u; tieCount = 0; }
    __syncthreads();

    #pragma unroll
    for (int pass = 0; pass < 4; ++pass) {
        int shift = 24 - 8 * pass;
        hist[t] = 0;
        __syncthreads();
        unsigned int pm   = (pass == 0) ? 0u : (0xFFFFFFFFu << (32 - 8 * pass));
        unsigned int pref = s_prefix;
        for (int i = t; i < S; i += 256) {
            unsigned int u = uvals[i];
            if ((u & pm) == pref)
                atomicAdd(&hist[(u >> shift) & 0xFF], 1);
        }
        __syncthreads();
        if (t == 0) {
            int r = s_r, cum = 0, bin = 0;
            for (bin = 0; bin < 256; ++bin) {
                int h = hist[bin];
                if (cum + h > r) break;
                cum += h;
            }
            s_r      = r - cum;
            s_less  += cum;
            s_prefix = pref | ((unsigned int)bin << shift);
        }
        __syncthreads();
    }

    unsigned int T = s_prefix;
    int zeroTies = RNUM - s_less;   // how many values == T to zero (index order)

    for (int i = t; i < S; i += 256) {
        unsigned int u = uvals[i];
        if (u < T) {
            yb[i] = 0.0f;
        } else if (u == T) {
            int p = atomicAdd(&tieCount, 1);
            if (p < 64) tieIdx[p] = i;
        }
    }
    __syncthreads();

    if (t == 0) {
        int tc = tieCount < 64 ? tieCount : 64;
        // tiny insertion sort of tie indices (expected tc == 1)
        for (int i = 1; i < tc; ++i) {
            int v = tieIdx[i], j = i - 1;
            while (j >= 0 && tieIdx[j] > v) { tieIdx[j + 1] = tieIdx[j]; --j; }
            tieIdx[j + 1] = v;
        }
        int z = zeroTies < tc ? zeroTies : tc;
        for (int j = 0; j < z; ++j) yb[tieIdx[j]] = 0.0f;
    }
}

// ---------------------------------------------------------------------------
// Kernel 5: broadcast masked map to all 256 channels (write-bound).
// ---------------------------------------------------------------------------
__global__ void bcast(float* __restrict__ out) {
    int gid = blockIdx.x * blockDim.x + threadIdx.x;   // 0 .. BATCH*CHAN*S4-1
    int row = gid / S4;          // b*256 + c
    int s4  = gid % S4;
    int b   = row >> 8;
    float4 v = __ldg(reinterpret_cast<const float4*>(g_y) + b * S4 + s4);
    reinterpret_cast<float4*>(out)[gid] = v;
}

// ---------------------------------------------------------------------------
extern "C" void kernel_launch(void* const* d_in, const int* in_sizes, int n_in,
                              void* d_out, int out_size) {
    const float* x = (const float*)d_in[0];   // [32,256,56,56]
    const float* w = (const float*)d_in[1];   // [1,2,3,3]
    float* out = (float*)d_out;               // [32,256,56,56]

    pool_partial<<<(QSPLIT * BATCH * S4) / 256, 256>>>(x);          // 392 blocks
    pool_combine<<<(BATCH * S4 + 255) / 256, 256>>>();              // 98 blocks
    conv_sig<<<(BATCH * S + 255) / 256, 256>>>(w);                  // 392 blocks
    topk_mask<<<BATCH, 256>>>();                                    // 32 blocks
    bcast<<<(BATCH * CHAN * S4) / 256, 256>>>(out);                 // 25088 blocks
}

// round 2
// speedup vs baseline: 1.3061x; 1.3061x over previous
#include <cuda_runtime.h>
#include <stdint.h>
#include <math.h>

#define BATCH 32
#define CHAN  256
#define HH    56
#define WW    56
#define S     (HH*WW)       // 3136
#define S4    (S/4)         // 784
#define QSPLIT 8
#define CQ    (CHAN/QSPLIT) // 32
#define RNUM  1568          // removed_num = round(3136*0.5)

// scratch (no cudaMalloc allowed)
__device__ __align__(16) float g_part_max[QSPLIT*BATCH*S];
__device__ __align__(16) float g_part_sum[QSPLIT*BATCH*S];
__device__ __align__(16) float g_y[BATCH*S];

// ---------------------------------------------------------------------------
// Kernel 1: partial channel max/sum. Each thread owns 4 consecutive spatial
// positions (float4) and 32 of the 256 channels. 784 blocks x 256 threads.
// Read-roofline kernel (~103 MB in).
// ---------------------------------------------------------------------------
__global__ void pool_partial(const float* __restrict__ x) {
    int gid = blockIdx.x * blockDim.x + threadIdx.x;   // 0 .. QSPLIT*BATCH*S4-1
    int q   = gid / (BATCH * S4);
    int rem = gid % (BATCH * S4);
    int b   = rem / S4;
    int s4  = rem % S4;

    const float4* p = reinterpret_cast<const float4*>(x)
                    + (size_t)(b * CHAN + q * CQ) * S4 + s4;

    float4 mx = make_float4(-INFINITY, -INFINITY, -INFINITY, -INFINITY);
    float4 sm = make_float4(0.f, 0.f, 0.f, 0.f);

    #pragma unroll 8
    for (int c = 0; c < CQ; ++c) {
        float4 v = __ldg(p + (size_t)c * S4);
        mx.x = fmaxf(mx.x, v.x); mx.y = fmaxf(mx.y, v.y);
        mx.z = fmaxf(mx.z, v.z); mx.w = fmaxf(mx.w, v.w);
        sm.x += v.x; sm.y += v.y; sm.z += v.z; sm.w += v.w;
    }

    int o = (q * BATCH + b) * S4 + s4;
    reinterpret_cast<float4*>(g_part_max)[o] = mx;
    reinterpret_cast<float4*>(g_part_sum)[o] = sm;
}

// ---------------------------------------------------------------------------
// Kernel 2 (fused): per batch -> combine partials, 3x3 conv + sigmoid,
// exact radix select of RNUM smallest, zero them, write masked map to g_y.
// One block per batch, 1024 threads. All intermediates in smem.
// Bin selection uses a parallel (Hillis-Steele) prefix over 256 bins.
// ---------------------------------------------------------------------------
__global__ void __launch_bounds__(1024, 1) fused_conv_topk(const float* __restrict__ w) {
    __shared__ float pm[S];                 // pooled max
    __shared__ float pa[S];                 // pooled avg
    __shared__ unsigned int uvals[S];       // sigmoid bits (positive -> uint order == float order)
    __shared__ int hist[256];
    __shared__ int scan[256];
    __shared__ float ws[18];
    __shared__ unsigned int s_prefix;
    __shared__ int s_r, s_less;
    __shared__ int tieIdx[256];
    __shared__ int tieCount;

    const int b = blockIdx.x;
    const int t = threadIdx.x;

    if (t < 18) ws[t] = w[t];
    if (t == 0) { s_r = RNUM - 1; s_less = 0; s_prefix = 0u; tieCount = 0; }

    // --- combine QSPLIT partials into pooled max / avg (smem) ---
    const float inv = 1.0f / (float)CHAN;
    for (int i = t; i < S; i += 1024) {
        float mx = -INFINITY, sm = 0.f;
        #pragma unroll
        for (int q = 0; q < QSPLIT; ++q) {
            int o = (q * BATCH + b) * S + i;
            mx = fmaxf(mx, g_part_max[o]);
            sm += g_part_sum[o];
        }
        pm[i] = mx;
        pa[i] = sm * inv;
    }
    __syncthreads();

    // --- 3x3 conv (2ch->1ch, pad 1, cross-correlation OIHW) + sigmoid ---
    for (int i = t; i < S; i += 1024) {
        int oh = i / WW, ow = i % WW;
        float acc = 0.f;
        #pragma unroll
        for (int ky = 0; ky < 3; ++ky) {
            int ih = oh + ky - 1;
            if (ih < 0 || ih >= HH) continue;
            #pragma unroll
            for (int kx = 0; kx < 3; ++kx) {
                int iw = ow + kx - 1;
                if (iw < 0 || iw >= WW) continue;
                int ii = ih * WW + iw;
                acc = fmaf(pm[ii], ws[ky * 3 + kx], acc);
                acc = fmaf(pa[ii], ws[9 + ky * 3 + kx], acc);
            }
        }
        float y = 1.0f / (1.0f + expf(-acc));
        uvals[i] = __float_as_uint(y);
    }
    __syncthreads();

    // --- 4-pass radix select (8 bits/pass), parallel bin prefix ---
    #pragma unroll
    for (int pass = 0; pass < 4; ++pass) {
        const int shift = 24 - 8 * pass;
        if (t < 256) hist[t] = 0;
        __syncthreads();

        const unsigned int pmask = (pass == 0) ? 0u : (0xFFFFFFFFu << (32 - 8 * pass));
        const unsigned int pref  = s_prefix;
        for (int i = t; i < S; i += 1024) {
            unsigned int u = uvals[i];
            if ((u & pmask) == pref)
                atomicAdd(&hist[(u >> shift) & 0xFF], 1);
        }
        __syncthreads();

        // inclusive prefix of hist -> scan (Hillis-Steele, all threads sync)
        if (t < 256) scan[t] = hist[t];
        __syncthreads();
        #pragma unroll
        for (int off = 1; off < 256; off <<= 1) {
            int v = 0;
            if (t < 256 && t >= off) v = scan[t - off];
            __syncthreads();
            if (t < 256) scan[t] += v;
            __syncthreads();
        }

        if (t < 256) {
            int incl = scan[t];
            int excl = incl - hist[t];
            int r = s_r;
            if (excl <= r && r < incl) {           // exactly one bin matches
                s_r      = r - excl;
                s_less  += excl;
                s_prefix = pref | ((unsigned int)t << shift);
            }
        }
        __syncthreads();
    }

    const unsigned int T = s_prefix;        // exact value at rank RNUM-1
    const int zeroTies = RNUM - s_less;     // # of values == T to zero (ascending index)

    float* yb = g_y + b * S;
    for (int i = t; i < S; i += 1024) {
        unsigned int u = uvals[i];
        float v = __uint_as_float(u);
        if (u < T) {
            v = 0.0f;
        } else if (u == T) {
            int p = atomicAdd(&tieCount, 1);
            if (p < 256) tieIdx[p] = i;
        }
        yb[i] = v;
    }
    __syncthreads();

    if (t == 0) {
        int tc = tieCount < 256 ? tieCount : 256;
        for (int i = 1; i < tc; ++i) {       // tiny insertion sort (expected tc==1)
            int v = tieIdx[i], j = i - 1;
            while (j >= 0 && tieIdx[j] > v) { tieIdx[j + 1] = tieIdx[j]; --j; }
            tieIdx[j + 1] = v;
        }
        int z = zeroTies < tc ? zeroTies : tc;
        for (int j = 0; j < z; ++j) yb[tieIdx[j]] = 0.0f;
    }
}

// ---------------------------------------------------------------------------
// Kernel 3: broadcast masked map to all 256 channels (write-roofline kernel).
// ---------------------------------------------------------------------------
__global__ void bcast(float* __restrict__ out) {
    int gid = blockIdx.x * blockDim.x + threadIdx.x;   // 0 .. BATCH*CHAN*S4-1
    int row = gid / S4;          // b*256 + c
    int s4  = gid % S4;
    int b   = row >> 8;
    float4 v = __ldg(reinterpret_cast<const float4*>(g_y) + b * S4 + s4);
    reinterpret_cast<float4*>(out)[gid] = v;
}

// ---------------------------------------------------------------------------
extern "C" void kernel_launch(void* const* d_in, const int* in_sizes, int n_in,
                              void* d_out, int out_size) {
    const float* x = (const float*)d_in[0];   // [32,256,56,56]
    const float* w = (const float*)d_in[1];   // [1,2,3,3]
    float* out = (float*)d_out;               // [32,256,56,56]

    pool_partial<<<(QSPLIT * BATCH * S4) / 256, 256>>>(x);   // 784 blocks
    fused_conv_topk<<<BATCH, 1024>>>(w);                     // 32 blocks
    bcast<<<(BATCH * CHAN * S4) / 256, 256>>>(out);          // 25088 blocks
}